// round 13
// baseline (speedup 1.0000x reference)
#include <cuda_runtime.h>
#include <cuda_fp16.h>
#include <math.h>

#define CDIM 768
#define EXP 8
#define HDIM 3072
#define MAXN 8192            // 2^13; pack = (e<<13)|slot

// ---- scratch (device globals; no cudaMalloc allowed) ----
__device__ int    d_fill[EXP];
__device__ int    d_off[EXP];
__device__ int    d_tok[EXP * MAXN];
__device__ float  d_wgt[EXP * MAXN];
__device__ int    d_slot[2 * MAXN];
__device__ int    d_tl[EXP * (MAXN / 128)];   // tile list: (e<<16)|mblock
__device__ int    d_ntl;
__device__ int    d_wq[2];                    // work counters (per GEMM)
__device__ __half d_xh[(size_t)MAXN * CDIM];
__device__ __half d_w1h[(size_t)EXP * CDIM * HDIM];
__device__ __half d_w2h[(size_t)EXP * HDIM * CDIM];
__device__ __half d_hbufh[(size_t)2 * MAXN * HDIM];
__device__ __half d_ybuf[(size_t)2 * MAXN * CDIM];

__device__ __forceinline__ unsigned smem_u32(const void* p) {
    unsigned a;
    asm("{ .reg .u64 t; cvta.to.shared.u64 t, %1; cvt.u32.u64 %0, t; }"
        : "=r"(a) : "l"(p));
    return a;
}

// fp32-accumulate MMA
__device__ __forceinline__ void mma_f16(float* c, const unsigned* a, const unsigned* b) {
    asm volatile(
        "mma.sync.aligned.m16n8k16.row.col.f32.f16.f16.f32 "
        "{%0,%1,%2,%3}, {%4,%5,%6,%7}, {%8,%9}, {%0,%1,%2,%3};"
        : "+f"(c[0]), "+f"(c[1]), "+f"(c[2]), "+f"(c[3])
        : "r"(a[0]), "r"(a[1]), "r"(a[2]), "r"(a[3]), "r"(b[0]), "r"(b[1]));
}

// fp16-accumulate MMA (2x rate)
__device__ __forceinline__ void mma_f16h(unsigned* d, const unsigned* a, const unsigned* b) {
    asm volatile(
        "mma.sync.aligned.m16n8k16.row.col.f16.f16.f16.f16 "
        "{%0,%1}, {%2,%3,%4,%5}, {%6,%7}, {%0,%1};"
        : "+r"(d[0]), "+r"(d[1])
        : "r"(a[0]), "r"(a[1]), "r"(a[2]), "r"(a[3]), "r"(b[0]), "r"(b[1]));
}

__device__ __forceinline__ void ldsm4(unsigned* r, unsigned addr) {
    asm volatile("ldmatrix.sync.aligned.m8n8.x4.shared.b16 {%0,%1,%2,%3}, [%4];"
                 : "=r"(r[0]), "=r"(r[1]), "=r"(r[2]), "=r"(r[3]) : "r"(addr));
}
__device__ __forceinline__ void ldsm4t(unsigned* r, unsigned addr) {
    asm volatile("ldmatrix.sync.aligned.m8n8.x4.trans.shared.b16 {%0,%1,%2,%3}, [%4];"
                 : "=r"(r[0]), "=r"(r[1]), "=r"(r[2]), "=r"(r[3]) : "r"(addr));
}

// ---------------------------------------------------------------------------
__global__ void reset_kernel() {
    if (threadIdx.x < EXP) d_fill[threadIdx.x] = 0;
}

// fp32 -> fp16, 8 elems/thread
__global__ void cvt_half_kernel(const float* __restrict__ in, __half* __restrict__ outp,
                                long n8) {
    long i = (long)blockIdx.x * blockDim.x + threadIdx.x;
    if (i < n8) {
        const float4* s = reinterpret_cast<const float4*>(in) + i * 2;
        float4 v0 = s[0], v1 = s[1];
        __half2 h0 = __floats2half2_rn(v0.x, v0.y);
        __half2 h1 = __floats2half2_rn(v0.z, v0.w);
        __half2 h2 = __floats2half2_rn(v1.x, v1.y);
        __half2 h3 = __floats2half2_rn(v1.z, v1.w);
        uint4 o;
        o.x = *reinterpret_cast<unsigned*>(&h0);
        o.y = *reinterpret_cast<unsigned*>(&h1);
        o.z = *reinterpret_cast<unsigned*>(&h2);
        o.w = *reinterpret_cast<unsigned*>(&h3);
        reinterpret_cast<uint4*>(outp)[i] = o;
    }
}

// ---------------------------------------------------------------------------
// router: 1 warp per token
// ---------------------------------------------------------------------------
__global__ void router_kernel(const float* __restrict__ x,
                              const float* __restrict__ Wr, int N) {
    int gw   = (blockIdx.x * blockDim.x + threadIdx.x) >> 5;
    int lane = threadIdx.x & 31;
    if (gw >= N) return;
    const float* xr = x + (size_t)gw * CDIM;

    float acc[EXP];
#pragma unroll
    for (int e = 0; e < EXP; e++) acc[e] = 0.0f;
    for (int k = lane; k < CDIM; k += 32) {
        float xv = xr[k];
        const float4* w4 = reinterpret_cast<const float4*>(Wr + (size_t)k * EXP);
        float4 w0 = w4[0], w1 = w4[1];
        acc[0] += xv * w0.x; acc[1] += xv * w0.y;
        acc[2] += xv * w0.z; acc[3] += xv * w0.w;
        acc[4] += xv * w1.x; acc[5] += xv * w1.y;
        acc[6] += xv * w1.z; acc[7] += xv * w1.w;
    }
#pragma unroll
    for (int e = 0; e < EXP; e++)
#pragma unroll
        for (int off = 16; off > 0; off >>= 1)
            acc[e] += __shfl_xor_sync(0xFFFFFFFFu, acc[e], off);

    if (lane == 0) {
        float m = acc[0];
#pragma unroll
        for (int e = 1; e < EXP; e++) m = fmaxf(m, acc[e]);
        float p[EXP], s = 0.0f;
#pragma unroll
        for (int e = 0; e < EXP; e++) { p[e] = expf(acc[e] - m); s += p[e]; }
        float inv = 1.0f / s;
#pragma unroll
        for (int e = 0; e < EXP; e++) p[e] *= inv;
        int i1 = 0;
#pragma unroll
        for (int e = 1; e < EXP; e++) if (p[e] > p[i1]) i1 = e;
        int i2 = (i1 == 0) ? 1 : 0;
#pragma unroll
        for (int e = 0; e < EXP; e++)
            if (e != i1 && p[e] > p[i2]) i2 = e;
        float denom = p[i1] + p[i2] + 1e-9f;
        float w1 = p[i1] / denom, w2 = p[i2] / denom;
        int s1 = atomicAdd(&d_fill[i1], 1);
        int p1 = (i1 << 13) | s1;
        d_tok[p1] = gw; d_wgt[p1] = w1; d_slot[gw] = p1;
        int s2 = atomicAdd(&d_fill[i2], 1);
        int p2 = (i2 << 13) | s2;
        d_tok[p2] = gw; d_wgt[p2] = w2; d_slot[MAXN + gw] = p2;
    }
}

// offsets + tile list + work-counter reset
__global__ void offsets_kernel() {
    if (threadIdx.x == 0) {
        int o = 0, m = 0;
        for (int e = 0; e < EXP; e++) {
            d_off[e] = o;
            int c = d_fill[e];
            o += c;
            int nb = (c + 127) / 128;
            for (int mb = 0; mb < nb; mb++) d_tl[m++] = (e << 16) | mb;
        }
        d_ntl = m;
        d_wq[0] = 0;
        d_wq[1] = 0;
    }
}

// ---------------------------------------------------------------------------
// Persistent fp16 mma.sync GEMM. CTA 128x256, BK=64, 512 thr, 16 warps
// (2m x 8n, warp 64x32), ldmatrix, 3-stage cp.async, 1 sync/iter.
// MODE 0: fp32-acc; A = gathered x rows -> gelu -> hbuf
// MODE 1: fp16-acc chained over K=64, promoted to fp32 per iter (2x tensor
//         rate); A = hbuf rows -> (y + b2) fp16 -> ybuf
// ---------------------------------------------------------------------------
#define GSMEM 148480
#define NSM 152

template<int KD, int ND, int MODE>
__global__ void __launch_bounds__(512, 1)
moe_gemm(const __half* __restrict__ Amat, const __half* __restrict__ Bmat,
         const float* __restrict__ bias) {
    constexpr int ITERS = KD / 64;
    constexpr int NJ    = ND / 256;

    extern __shared__ char smem[];
    int* stok = reinterpret_cast<int*>(smem);
    int* s_t  = reinterpret_cast<int*>(smem + 768);
    const unsigned sA = smem_u32(smem + 1024);          // 3 x 16384
    const unsigned sB = sA + 49152;                     // 3 x 32768

    const int tid = threadIdx.x;
    const int lane = tid & 31, w = tid >> 5;
    const int wm = (w & 1) * 64, wn = (w >> 1) * 32;
    const int rsel = (lane & 7) | (lane & 8);
    const int kh   = (lane >> 4) & 1;
    const int l7   = lane & 7;

    const int NT = d_ntl * NJ;

    for (;;) {
        __syncthreads();   // prior tile's smem reads complete before reuse
        if (tid == 0) *s_t = atomicAdd(&d_wq[MODE], 1);
        __syncthreads();
        const int t = *s_t;
        if (t >= NT) break;

        const int pair = d_tl[t / NJ];
        const int e    = pair >> 16;
        const int m0   = (pair & 0xFFFF) * 128;
        const int j0   = (t % NJ) * 256;
        const int cnt  = d_fill[e];
        const int off  = d_off[e];

        if (MODE == 0 && tid < 128) {
            int gm = m0 + tid;
            stok[tid] = (gm < cnt) ? d_tok[(e << 13) | gm] : -1;
        }
        __syncthreads();

        // ---- cp.async slots: A 2 chunks, B 4 chunks per thread (16B) ----
        const __half* agp[2]; unsigned aso[2], asz[2];
#pragma unroll
        for (int tt = 0; tt < 2; tt++) {
            int idx = tid + tt * 512, row = idx >> 3, c = idx & 7;
            bool ok; size_t base;
            if (MODE == 0) { int tk = stok[row]; ok = (tk >= 0); base = ok ? (size_t)tk * KD : 0; }
            else           { int gm = m0 + row;  ok = (gm < cnt); base = ok ? (size_t)(off + gm) * KD : 0; }
            agp[tt] = Amat + base + c * 8;
            asz[tt] = ok ? 16u : 0u;
            aso[tt] = row * 128 + ((c ^ (row & 7)) * 16);
        }
        const __half* bbase = Bmat + (size_t)e * CDIM * HDIM + j0;
        int bgo[4]; unsigned bso[4];
#pragma unroll
        for (int tt = 0; tt < 4; tt++) {
            int idx = tid + tt * 512, row = idx >> 5, c = idx & 31;
            bgo[tt] = row * ND + c * 8;
            bso[tt] = row * 512 + ((c ^ (row & 7)) * 16);
        }

        auto load_tile = [&](int p, int k0) {
            unsigned Ab = sA + p * 16384, Bb = sB + p * 32768;
#pragma unroll
            for (int tt = 0; tt < 2; tt++)
                asm volatile("cp.async.cg.shared.global [%0], [%1], 16, %2;"
                             :: "r"(Ab + aso[tt]), "l"(agp[tt] + k0), "r"(asz[tt]) : "memory");
            const __half* bsrc = bbase + (size_t)k0 * ND;
#pragma unroll
            for (int tt = 0; tt < 4; tt++)
                asm volatile("cp.async.cg.shared.global [%0], [%1], 16;"
                             :: "r"(Bb + bso[tt]), "l"(bsrc + bgo[tt]) : "memory");
        };

        float acc[4][4][4];
#pragma unroll
        for (int mt = 0; mt < 4; mt++)
#pragma unroll
            for (int nt = 0; nt < 4; nt++)
#pragma unroll
                for (int i = 0; i < 4; i++) acc[mt][nt][i] = 0.0f;

        load_tile(0, 0);
        asm volatile("cp.async.commit_group;" ::: "memory");
        load_tile(1, 64);
        asm volatile("cp.async.commit_group;" ::: "memory");

        for (int i = 0; i < ITERS; i++) {
            const int p = i % 3;
            asm volatile("cp.async.wait_group 1;" ::: "memory");
            __syncthreads();
            if (i + 2 < ITERS) load_tile((i + 2) % 3, (i + 2) * 64);
            asm volatile("cp.async.commit_group;" ::: "memory");

            const unsigned Ab = sA + p * 16384, Bb = sB + p * 32768;

            unsigned c16[4][4][2];
            if (MODE == 1) {
#pragma unroll
                for (int mt = 0; mt < 4; mt++)
#pragma unroll
                    for (int nt = 0; nt < 4; nt++) {
                        c16[mt][nt][0] = 0u;
                        c16[mt][nt][1] = 0u;
                    }
            }

#pragma unroll
            for (int ks = 0; ks < 4; ks++) {
                unsigned afr[4][4];
#pragma unroll
                for (int mt = 0; mt < 4; mt++) {
                    unsigned ad = Ab + (wm + mt * 16 + rsel) * 128
                                + (((ks * 2 + kh) ^ l7) * 16);
                    ldsm4(afr[mt], ad);
                }
                unsigned bfr[4][2];
#pragma unroll
                for (int bt = 0; bt < 2; bt++) {
                    int krow = ks * 16 + rsel;
                    unsigned bd = Bb + krow * 512
                                + ((((wn >> 3) + bt * 2 + kh) ^ l7) * 16);
                    unsigned r[4];
                    ldsm4t(r, bd);
                    bfr[bt * 2][0] = r[0];     bfr[bt * 2][1] = r[1];
                    bfr[bt * 2 + 1][0] = r[2]; bfr[bt * 2 + 1][1] = r[3];
                }
#pragma unroll
                for (int mt = 0; mt < 4; mt++)
#pragma unroll
                    for (int nt = 0; nt < 4; nt++) {
                        if (MODE == 0) mma_f16(acc[mt][nt], afr[mt], bfr[nt]);
                        else           mma_f16h(c16[mt][nt], afr[mt], bfr[nt]);
                    }
            }

            if (MODE == 1) {
                // promote K=64 fp16 partials into fp32 accumulators
#pragma unroll
                for (int mt = 0; mt < 4; mt++)
#pragma unroll
                    for (int nt = 0; nt < 4; nt++) {
                        __half2 h0 = *reinterpret_cast<__half2*>(&c16[mt][nt][0]);
                        __half2 h1 = *reinterpret_cast<__half2*>(&c16[mt][nt][1]);
                        float2 f0 = __half22float2(h0);
                        float2 f1 = __half22float2(h1);
                        acc[mt][nt][0] += f0.x;
                        acc[mt][nt][1] += f0.y;
                        acc[mt][nt][2] += f1.x;
                        acc[mt][nt][3] += f1.y;
                    }
            }
        }

        // ---- epilogue ----
#pragma unroll
        for (int mt = 0; mt < 4; mt++) {
#pragma unroll
            for (int half = 0; half < 2; half++) {
                int lrow = wm + mt * 16 + (lane >> 2) + half * 8;
                int gm   = m0 + lrow;
                if (gm >= cnt) continue;
                __half* hrow = (MODE == 0)
                    ? (d_hbufh + (size_t)(off + gm) * HDIM)
                    : (d_ybuf  + (size_t)(off + gm) * CDIM);
#pragma unroll
                for (int nt = 0; nt < 4; nt++) {
                    int col = j0 + wn + nt * 8 + (lane & 3) * 2;
                    float v0 = acc[mt][nt][half * 2 + 0] + bias[(size_t)e * ND + col];
                    float v1 = acc[mt][nt][half * 2 + 1] + bias[(size_t)e * ND + col + 1];
                    if (MODE == 0) {
                        v0 = 0.5f * v0 * (1.0f + erff(v0 * 0.70710678118654752f));
                        v1 = 0.5f * v1 * (1.0f + erff(v1 * 0.70710678118654752f));
                    }
                    *reinterpret_cast<__half2*>(hrow + col) = __floats2half2_rn(v0, v1);
                }
            }
        }
    }
}

// ---------------------------------------------------------------------------
// combine: out[tok] = w1*ybuf[row1] + w2*ybuf[row2]
// ---------------------------------------------------------------------------
__global__ void combine_kernel(float* __restrict__ out, int N) {
    int gid  = blockIdx.x * blockDim.x + threadIdx.x;
    int col4 = gid * 4;
    int tok  = col4 / CDIM;
    int c    = col4 % CDIM;
    if (tok >= N) return;

    int p1 = d_slot[tok], p2 = d_slot[MAXN + tok];
    int r1 = d_off[p1 >> 13] + (p1 & (MAXN - 1));
    int r2 = d_off[p2 >> 13] + (p2 & (MAXN - 1));
    float w1 = d_wgt[p1], w2 = d_wgt[p2];

    const __half2* a = reinterpret_cast<const __half2*>(d_ybuf + (size_t)r1 * CDIM + c);
    const __half2* b = reinterpret_cast<const __half2*>(d_ybuf + (size_t)r2 * CDIM + c);
    float2 a0 = __half22float2(a[0]), a1 = __half22float2(a[1]);
    float2 b0 = __half22float2(b[0]), b1 = __half22float2(b[1]);
    float4 o;
    o.x = w1 * a0.x + w2 * b0.x;
    o.y = w1 * a0.y + w2 * b0.y;
    o.z = w1 * a1.x + w2 * b1.x;
    o.w = w1 * a1.y + w2 * b1.y;
    *reinterpret_cast<float4*>(out + (size_t)tok * CDIM + c) = o;
}

// ---------------------------------------------------------------------------
__global__ void util_kernel(float* __restrict__ out, int NC) {
    int e = threadIdx.x;
    if (e < EXP) {
        float tot = 0.0f;
        for (int j = 0; j < EXP; j++) tot += (float)d_fill[j];
        out[NC + e] = (float)d_fill[e] / (tot + 1e-9f);
    }
}

// ---------------------------------------------------------------------------
extern "C" void kernel_launch(void* const* d_in, const int* in_sizes, int n_in,
                              void* d_out, int out_size) {
    const float* x  = (const float*)d_in[0];
    const float* Wr = (const float*)d_in[1];
    const float* W1 = (const float*)d_in[2];
    const float* b1 = (const float*)d_in[3];
    const float* W2 = (const float*)d_in[4];
    const float* b2 = (const float*)d_in[5];
    float* out = (float*)d_out;

    int N  = in_sizes[0] / CDIM;   // 8192
    int NC = N * CDIM;

    static cudaStream_t s1 = nullptr, s2 = nullptr;
    static cudaEvent_t evRoot, evX, evW1b, evW2;
    static int init_done = 0;
    if (!init_done) {
        cudaFuncSetAttribute(moe_gemm<CDIM, HDIM, 0>,
                             cudaFuncAttributeMaxDynamicSharedMemorySize, GSMEM);
        cudaFuncSetAttribute(moe_gemm<HDIM, CDIM, 1>,
                             cudaFuncAttributeMaxDynamicSharedMemorySize, GSMEM);
        cudaStreamCreateWithFlags(&s1, cudaStreamNonBlocking);
        cudaStreamCreateWithFlags(&s2, cudaStreamNonBlocking);
        cudaEventCreateWithFlags(&evRoot, cudaEventDisableTiming);
        cudaEventCreateWithFlags(&evX, cudaEventDisableTiming);
        cudaEventCreateWithFlags(&evW1b, cudaEventDisableTiming);
        cudaEventCreateWithFlags(&evW2, cudaEventDisableTiming);
        init_done = 1;
    }

    __half *xh, *w1h, *w2h;
    cudaGetSymbolAddress((void**)&xh,  d_xh);
    cudaGetSymbolAddress((void**)&w1h, d_w1h);
    cudaGetSymbolAddress((void**)&w2h, d_w2h);

    // ---- fork: converts on s1/s2, routing on main ----
    cudaEventRecord(evRoot, 0);
    cudaStreamWaitEvent(s1, evRoot, 0);
    cudaStreamWaitEvent(s2, evRoot, 0);

    reset_kernel<<<1, 32>>>();
    router_kernel<<<(N + 7) / 8, 256>>>(x, Wr, N);
    offsets_kernel<<<1, 32>>>();

    {
        long nw  = (long)EXP * CDIM * HDIM;      // elements per weight tensor
        long h8  = nw / 2 / 8;                   // 8-elem chunks per half
        // W1 split across both streams, then x on s1, W2 on s2
        cvt_half_kernel<<<(int)((h8 + 255) / 256), 256, 0, s1>>>(W1, w1h, h8);
        cvt_half_kernel<<<(int)((h8 + 255) / 256), 256, 0, s2>>>(W1 + nw / 2, w1h + nw / 2, h8);
        cudaEventRecord(evW1b, s2);
        cvt_half_kernel<<<(NC / 8 + 255) / 256, 256, 0, s1>>>(x, xh, NC / 8);
        cudaEventRecord(evX, s1);
        cvt_half_kernel<<<(int)((nw / 8 + 255) / 256), 256, 0, s2>>>(W2, w2h, nw / 8);
    }
    cudaEventRecord(evW2, s2);

    // ---- gemm1: needs routing, xh, both W1 halves ----
    cudaStreamWaitEvent(0, evX, 0);
    cudaStreamWaitEvent(0, evW1b, 0);
    moe_gemm<CDIM, HDIM, 0><<<NSM, 512, GSMEM>>>(xh, w1h, b1);

    // ---- gemm2: needs w2h ----
    cudaStreamWaitEvent(0, evW2, 0);
    __half* hb; cudaGetSymbolAddress((void**)&hb, d_hbufh);
    moe_gemm<HDIM, CDIM, 1><<<NSM, 512, GSMEM>>>(hb, w2h, b2);

    combine_kernel<<<(NC / 4 + 255) / 256, 256>>>(out, N);
    util_kernel<<<1, 32>>>(out, NC);
}

// round 14
// speedup vs baseline: 1.1283x; 1.1283x over previous
#include <cuda_runtime.h>
#include <cuda_fp16.h>
#include <math.h>

#define CDIM 768
#define EXP 8
#define HDIM 3072
#define MAXN 8192            // 2^13; pack = (e<<13)|slot

// ---- scratch (device globals; no cudaMalloc allowed) ----
__device__ int    d_fill[EXP];
__device__ int    d_off[EXP];
__device__ int    d_tok[EXP * MAXN];
__device__ float  d_wgt[EXP * MAXN];
__device__ int    d_slot[2 * MAXN];
__device__ int    d_tl[EXP * (MAXN / 128)];   // tile list: (e<<16)|mblock
__device__ int    d_ntl;
__device__ int    d_wq[2];                    // work counters (per GEMM)
__device__ __half d_xh[(size_t)MAXN * CDIM];
__device__ __half d_w1h[(size_t)EXP * CDIM * HDIM];
__device__ __half d_w2h[(size_t)EXP * HDIM * CDIM];
__device__ __half d_hbufh[(size_t)2 * MAXN * HDIM];
__device__ __half d_ybuf[(size_t)2 * MAXN * CDIM];

__device__ __forceinline__ unsigned smem_u32(const void* p) {
    unsigned a;
    asm("{ .reg .u64 t; cvta.to.shared.u64 t, %1; cvt.u32.u64 %0, t; }"
        : "=r"(a) : "l"(p));
    return a;
}

__device__ __forceinline__ void mma_f16(float* c, const unsigned* a, const unsigned* b) {
    asm volatile(
        "mma.sync.aligned.m16n8k16.row.col.f32.f16.f16.f32 "
        "{%0,%1,%2,%3}, {%4,%5,%6,%7}, {%8,%9}, {%0,%1,%2,%3};"
        : "+f"(c[0]), "+f"(c[1]), "+f"(c[2]), "+f"(c[3])
        : "r"(a[0]), "r"(a[1]), "r"(a[2]), "r"(a[3]), "r"(b[0]), "r"(b[1]));
}

__device__ __forceinline__ void ldsm4(unsigned* r, unsigned addr) {
    asm volatile("ldmatrix.sync.aligned.m8n8.x4.shared.b16 {%0,%1,%2,%3}, [%4];"
                 : "=r"(r[0]), "=r"(r[1]), "=r"(r[2]), "=r"(r[3]) : "r"(addr));
}
__device__ __forceinline__ void ldsm4t(unsigned* r, unsigned addr) {
    asm volatile("ldmatrix.sync.aligned.m8n8.x4.trans.shared.b16 {%0,%1,%2,%3}, [%4];"
                 : "=r"(r[0]), "=r"(r[1]), "=r"(r[2]), "=r"(r[3]) : "r"(addr));
}

// ---------------------------------------------------------------------------
__global__ void reset_kernel() {
    if (threadIdx.x < EXP) d_fill[threadIdx.x] = 0;
}

// fp32 -> fp16, 8 elems/thread
__global__ void cvt_half_kernel(const float* __restrict__ in, __half* __restrict__ outp,
                                long n8) {
    long i = (long)blockIdx.x * blockDim.x + threadIdx.x;
    if (i < n8) {
        const float4* s = reinterpret_cast<const float4*>(in) + i * 2;
        float4 v0 = s[0], v1 = s[1];
        __half2 h0 = __floats2half2_rn(v0.x, v0.y);
        __half2 h1 = __floats2half2_rn(v0.z, v0.w);
        __half2 h2 = __floats2half2_rn(v1.x, v1.y);
        __half2 h3 = __floats2half2_rn(v1.z, v1.w);
        uint4 o;
        o.x = *reinterpret_cast<unsigned*>(&h0);
        o.y = *reinterpret_cast<unsigned*>(&h1);
        o.z = *reinterpret_cast<unsigned*>(&h2);
        o.w = *reinterpret_cast<unsigned*>(&h3);
        reinterpret_cast<uint4*>(outp)[i] = o;
    }
}

// ---------------------------------------------------------------------------
// router: 1 warp per token
// ---------------------------------------------------------------------------
__global__ void router_kernel(const float* __restrict__ x,
                              const float* __restrict__ Wr, int N) {
    int gw   = (blockIdx.x * blockDim.x + threadIdx.x) >> 5;
    int lane = threadIdx.x & 31;
    if (gw >= N) return;
    const float* xr = x + (size_t)gw * CDIM;

    float acc[EXP];
#pragma unroll
    for (int e = 0; e < EXP; e++) acc[e] = 0.0f;
    for (int k = lane; k < CDIM; k += 32) {
        float xv = xr[k];
        const float4* w4 = reinterpret_cast<const float4*>(Wr + (size_t)k * EXP);
        float4 w0 = w4[0], w1 = w4[1];
        acc[0] += xv * w0.x; acc[1] += xv * w0.y;
        acc[2] += xv * w0.z; acc[3] += xv * w0.w;
        acc[4] += xv * w1.x; acc[5] += xv * w1.y;
        acc[6] += xv * w1.z; acc[7] += xv * w1.w;
    }
#pragma unroll
    for (int e = 0; e < EXP; e++)
#pragma unroll
        for (int off = 16; off > 0; off >>= 1)
            acc[e] += __shfl_xor_sync(0xFFFFFFFFu, acc[e], off);

    if (lane == 0) {
        float m = acc[0];
#pragma unroll
        for (int e = 1; e < EXP; e++) m = fmaxf(m, acc[e]);
        float p[EXP], s = 0.0f;
#pragma unroll
        for (int e = 0; e < EXP; e++) { p[e] = expf(acc[e] - m); s += p[e]; }
        float inv = 1.0f / s;
#pragma unroll
        for (int e = 0; e < EXP; e++) p[e] *= inv;
        int i1 = 0;
#pragma unroll
        for (int e = 1; e < EXP; e++) if (p[e] > p[i1]) i1 = e;
        int i2 = (i1 == 0) ? 1 : 0;
#pragma unroll
        for (int e = 0; e < EXP; e++)
            if (e != i1 && p[e] > p[i2]) i2 = e;
        float denom = p[i1] + p[i2] + 1e-9f;
        float w1 = p[i1] / denom, w2 = p[i2] / denom;
        int s1 = atomicAdd(&d_fill[i1], 1);
        int p1 = (i1 << 13) | s1;
        d_tok[p1] = gw; d_wgt[p1] = w1; d_slot[gw] = p1;
        int s2 = atomicAdd(&d_fill[i2], 1);
        int p2 = (i2 << 13) | s2;
        d_tok[p2] = gw; d_wgt[p2] = w2; d_slot[MAXN + gw] = p2;
    }
}

// offsets + tile list + work-counter reset
__global__ void offsets_kernel() {
    if (threadIdx.x == 0) {
        int o = 0, m = 0;
        for (int e = 0; e < EXP; e++) {
            d_off[e] = o;
            int c = d_fill[e];
            o += c;
            int nb = (c + 127) / 128;
            for (int mb = 0; mb < nb; mb++) d_tl[m++] = (e << 16) | mb;
        }
        d_ntl = m;
        d_wq[0] = 0;
        d_wq[1] = 0;
    }
}

// ---------------------------------------------------------------------------
// Persistent fp16 mma.sync GEMM (f32 accumulate). CTA 128x256, BK=64,
// 512 thr, 16 warps (2m x 8n, warp 64x32), ldmatrix, 3-stage cp.async,
// 1 sync/iter. Tiles pulled from d_wq[MODE] (work stealing).
// MODE 0: A = gathered x rows -> gelu -> hbuf
// MODE 1: A = hbuf rows -> (y + b2) fp16 -> ybuf
// ---------------------------------------------------------------------------
#define GSMEM 148480
#define NSM 152

template<int KD, int ND, int MODE>
__global__ void __launch_bounds__(512, 1)
moe_gemm(const __half* __restrict__ Amat, const __half* __restrict__ Bmat,
         const float* __restrict__ bias) {
    constexpr int ITERS = KD / 64;
    constexpr int NJ    = ND / 256;

    extern __shared__ char smem[];
    int* stok = reinterpret_cast<int*>(smem);
    int* s_t  = reinterpret_cast<int*>(smem + 768);
    const unsigned sA = smem_u32(smem + 1024);          // 3 x 16384
    const unsigned sB = sA + 49152;                     // 3 x 32768

    const int tid = threadIdx.x;
    const int lane = tid & 31, w = tid >> 5;
    const int wm = (w & 1) * 64, wn = (w >> 1) * 32;
    const int rsel = (lane & 7) | (lane & 8);
    const int kh   = (lane >> 4) & 1;
    const int l7   = lane & 7;

    const int NT = d_ntl * NJ;

    for (;;) {
        __syncthreads();   // prior tile's smem reads complete before reuse
        if (tid == 0) *s_t = atomicAdd(&d_wq[MODE], 1);
        __syncthreads();
        const int t = *s_t;
        if (t >= NT) break;

        const int pair = d_tl[t / NJ];
        const int e    = pair >> 16;
        const int m0   = (pair & 0xFFFF) * 128;
        const int j0   = (t % NJ) * 256;
        const int cnt  = d_fill[e];
        const int off  = d_off[e];

        if (MODE == 0 && tid < 128) {
            int gm = m0 + tid;
            stok[tid] = (gm < cnt) ? d_tok[(e << 13) | gm] : -1;
        }
        __syncthreads();

        // ---- cp.async slots: A 2 chunks, B 4 chunks per thread (16B) ----
        const __half* agp[2]; unsigned aso[2], asz[2];
#pragma unroll
        for (int tt = 0; tt < 2; tt++) {
            int idx = tid + tt * 512, row = idx >> 3, c = idx & 7;
            bool ok; size_t base;
            if (MODE == 0) { int tk = stok[row]; ok = (tk >= 0); base = ok ? (size_t)tk * KD : 0; }
            else           { int gm = m0 + row;  ok = (gm < cnt); base = ok ? (size_t)(off + gm) * KD : 0; }
            agp[tt] = Amat + base + c * 8;
            asz[tt] = ok ? 16u : 0u;
            aso[tt] = row * 128 + ((c ^ (row & 7)) * 16);
        }
        const __half* bbase = Bmat + (size_t)e * CDIM * HDIM + j0;
        int bgo[4]; unsigned bso[4];
#pragma unroll
        for (int tt = 0; tt < 4; tt++) {
            int idx = tid + tt * 512, row = idx >> 5, c = idx & 31;
            bgo[tt] = row * ND + c * 8;
            bso[tt] = row * 512 + ((c ^ (row & 7)) * 16);
        }

        auto load_tile = [&](int p, int k0) {
            unsigned Ab = sA + p * 16384, Bb = sB + p * 32768;
#pragma unroll
            for (int tt = 0; tt < 2; tt++)
                asm volatile("cp.async.cg.shared.global [%0], [%1], 16, %2;"
                             :: "r"(Ab + aso[tt]), "l"(agp[tt] + k0), "r"(asz[tt]) : "memory");
            const __half* bsrc = bbase + (size_t)k0 * ND;
#pragma unroll
            for (int tt = 0; tt < 4; tt++)
                asm volatile("cp.async.cg.shared.global [%0], [%1], 16;"
                             :: "r"(Bb + bso[tt]), "l"(bsrc + bgo[tt]) : "memory");
        };

        float acc[4][4][4];
#pragma unroll
        for (int mt = 0; mt < 4; mt++)
#pragma unroll
            for (int nt = 0; nt < 4; nt++)
#pragma unroll
                for (int i = 0; i < 4; i++) acc[mt][nt][i] = 0.0f;

        load_tile(0, 0);
        asm volatile("cp.async.commit_group;" ::: "memory");
        load_tile(1, 64);
        asm volatile("cp.async.commit_group;" ::: "memory");

        for (int i = 0; i < ITERS; i++) {
            const int p = i % 3;
            asm volatile("cp.async.wait_group 1;" ::: "memory");
            __syncthreads();
            if (i + 2 < ITERS) load_tile((i + 2) % 3, (i + 2) * 64);
            asm volatile("cp.async.commit_group;" ::: "memory");

            const unsigned Ab = sA + p * 16384, Bb = sB + p * 32768;
#pragma unroll
            for (int ks = 0; ks < 4; ks++) {
                unsigned afr[4][4];
#pragma unroll
                for (int mt = 0; mt < 4; mt++) {
                    unsigned ad = Ab + (wm + mt * 16 + rsel) * 128
                                + (((ks * 2 + kh) ^ l7) * 16);
                    ldsm4(afr[mt], ad);
                }
                unsigned bfr[4][2];
#pragma unroll
                for (int bt = 0; bt < 2; bt++) {
                    int krow = ks * 16 + rsel;
                    unsigned bd = Bb + krow * 512
                                + ((((wn >> 3) + bt * 2 + kh) ^ l7) * 16);
                    unsigned r[4];
                    ldsm4t(r, bd);
                    bfr[bt * 2][0] = r[0];     bfr[bt * 2][1] = r[1];
                    bfr[bt * 2 + 1][0] = r[2]; bfr[bt * 2 + 1][1] = r[3];
                }
#pragma unroll
                for (int mt = 0; mt < 4; mt++)
#pragma unroll
                    for (int nt = 0; nt < 4; nt++)
                        mma_f16(acc[mt][nt], afr[mt], bfr[nt]);
            }
        }

        // ---- epilogue ----
#pragma unroll
        for (int mt = 0; mt < 4; mt++) {
#pragma unroll
            for (int half = 0; half < 2; half++) {
                int lrow = wm + mt * 16 + (lane >> 2) + half * 8;
                int gm   = m0 + lrow;
                if (gm >= cnt) continue;
                __half* hrow = (MODE == 0)
                    ? (d_hbufh + (size_t)(off + gm) * HDIM)
                    : (d_ybuf  + (size_t)(off + gm) * CDIM);
#pragma unroll
                for (int nt = 0; nt < 4; nt++) {
                    int col = j0 + wn + nt * 8 + (lane & 3) * 2;
                    float v0 = acc[mt][nt][half * 2 + 0] + bias[(size_t)e * ND + col];
                    float v1 = acc[mt][nt][half * 2 + 1] + bias[(size_t)e * ND + col + 1];
                    if (MODE == 0) {
                        v0 = 0.5f * v0 * (1.0f + erff(v0 * 0.70710678118654752f));
                        v1 = 0.5f * v1 * (1.0f + erff(v1 * 0.70710678118654752f));
                    }
                    *reinterpret_cast<__half2*>(hrow + col) = __floats2half2_rn(v0, v1);
                }
            }
        }
    }
}

// ---------------------------------------------------------------------------
// combine: out[tok] = w1*ybuf[row1] + w2*ybuf[row2]
// ---------------------------------------------------------------------------
__global__ void combine_kernel(float* __restrict__ out, int N) {
    int gid  = blockIdx.x * blockDim.x + threadIdx.x;
    int col4 = gid * 4;
    int tok  = col4 / CDIM;
    int c    = col4 % CDIM;
    if (tok >= N) return;

    int p1 = d_slot[tok], p2 = d_slot[MAXN + tok];
    int r1 = d_off[p1 >> 13] + (p1 & (MAXN - 1));
    int r2 = d_off[p2 >> 13] + (p2 & (MAXN - 1));
    float w1 = d_wgt[p1], w2 = d_wgt[p2];

    const __half2* a = reinterpret_cast<const __half2*>(d_ybuf + (size_t)r1 * CDIM + c);
    const __half2* b = reinterpret_cast<const __half2*>(d_ybuf + (size_t)r2 * CDIM + c);
    float2 a0 = __half22float2(a[0]), a1 = __half22float2(a[1]);
    float2 b0 = __half22float2(b[0]), b1 = __half22float2(b[1]);
    float4 o;
    o.x = w1 * a0.x + w2 * b0.x;
    o.y = w1 * a0.y + w2 * b0.y;
    o.z = w1 * a1.x + w2 * b1.x;
    o.w = w1 * a1.y + w2 * b1.y;
    *reinterpret_cast<float4*>(out + (size_t)tok * CDIM + c) = o;
}

// ---------------------------------------------------------------------------
__global__ void util_kernel(float* __restrict__ out, int NC) {
    int e = threadIdx.x;
    if (e < EXP) {
        float tot = 0.0f;
        for (int j = 0; j < EXP; j++) tot += (float)d_fill[j];
        out[NC + e] = (float)d_fill[e] / (tot + 1e-9f);
    }
}

// ---------------------------------------------------------------------------
extern "C" void kernel_launch(void* const* d_in, const int* in_sizes, int n_in,
                              void* d_out, int out_size) {
    const float* x  = (const float*)d_in[0];
    const float* Wr = (const float*)d_in[1];
    const float* W1 = (const float*)d_in[2];
    const float* b1 = (const float*)d_in[3];
    const float* W2 = (const float*)d_in[4];
    const float* b2 = (const float*)d_in[5];
    float* out = (float*)d_out;

    int N  = in_sizes[0] / CDIM;   // 8192
    int NC = N * CDIM;

    static cudaStream_t s1 = nullptr, s2 = nullptr;
    static cudaEvent_t evRoot, evX, evW1b, evW2, evRoute;
    static int init_done = 0;
    if (!init_done) {
        cudaFuncSetAttribute(moe_gemm<CDIM, HDIM, 0>,
                             cudaFuncAttributeMaxDynamicSharedMemorySize, GSMEM);
        cudaFuncSetAttribute(moe_gemm<HDIM, CDIM, 1>,
                             cudaFuncAttributeMaxDynamicSharedMemorySize, GSMEM);
        cudaStreamCreateWithFlags(&s1, cudaStreamNonBlocking);
        cudaStreamCreateWithFlags(&s2, cudaStreamNonBlocking);
        cudaEventCreateWithFlags(&evRoot, cudaEventDisableTiming);
        cudaEventCreateWithFlags(&evX, cudaEventDisableTiming);
        cudaEventCreateWithFlags(&evW1b, cudaEventDisableTiming);
        cudaEventCreateWithFlags(&evW2, cudaEventDisableTiming);
        cudaEventCreateWithFlags(&evRoute, cudaEventDisableTiming);
        init_done = 1;
    }

    __half *xh, *w1h, *w2h;
    cudaGetSymbolAddress((void**)&xh,  d_xh);
    cudaGetSymbolAddress((void**)&w1h, d_w1h);
    cudaGetSymbolAddress((void**)&w2h, d_w2h);

    // ---- fork: converts on s1/s2, routing on main ----
    cudaEventRecord(evRoot, 0);
    cudaStreamWaitEvent(s1, evRoot, 0);
    cudaStreamWaitEvent(s2, evRoot, 0);

    reset_kernel<<<1, 32>>>();
    router_kernel<<<(N + 7) / 8, 256>>>(x, Wr, N);
    offsets_kernel<<<1, 32>>>();
    cudaEventRecord(evRoute, 0);

    {
        long nw  = (long)EXP * CDIM * HDIM;      // elements per weight tensor
        long h8  = nw / 2 / 8;                   // 8-elem chunks per half
        // W1 split across both streams, then x on s1, W2 on s2
        cvt_half_kernel<<<(int)((h8 + 255) / 256), 256, 0, s1>>>(W1, w1h, h8);
        cvt_half_kernel<<<(int)((h8 + 255) / 256), 256, 0, s2>>>(W1 + nw / 2, w1h + nw / 2, h8);
        cudaEventRecord(evW1b, s2);
        cvt_half_kernel<<<(NC / 8 + 255) / 256, 256, 0, s1>>>(x, xh, NC / 8);
        cudaEventRecord(evX, s1);
        cvt_half_kernel<<<(int)((nw / 8 + 255) / 256), 256, 0, s2>>>(W2, w2h, nw / 8);
    }
    cudaEventRecord(evW2, s2);

    // util is independent of the GEMMs: run it on s1 once routing is done
    cudaStreamWaitEvent(s1, evRoute, 0);
    util_kernel<<<1, 32, 0, s1>>>(out, NC);

    // ---- gemm1: needs routing, xh, both W1 halves ----
    cudaStreamWaitEvent(0, evX, 0);
    cudaStreamWaitEvent(0, evW1b, 0);
    moe_gemm<CDIM, HDIM, 0><<<NSM, 512, GSMEM>>>(xh, w1h, b1);

    // ---- gemm2: needs w2h ----
    cudaStreamWaitEvent(0, evW2, 0);
    __half* hb; cudaGetSymbolAddress((void**)&hb, d_hbufh);
    moe_gemm<HDIM, CDIM, 1><<<NSM, 512, GSMEM>>>(hb, w2h, b2);

    // combine joins gemm2 (main) and must also be ordered after util's writer
    cudaEventRecord(evRoot, s1);
    cudaStreamWaitEvent(0, evRoot, 0);
    combine_kernel<<<(NC / 4 + 255) / 256, 256>>>(out, N);
}

// round 17
// speedup vs baseline: 1.1326x; 1.0038x over previous
#include <cuda_runtime.h>
#include <cuda_fp16.h>
#include <math.h>

#define CDIM 768
#define EXP 8
#define HDIM 3072
#define MAXN 8192            // 2^13; pack = (e<<13)|slot

// ---- scratch (device globals; no cudaMalloc allowed) ----
__device__ int    d_fill[EXP];                // zero-init; reset at end of combine
__device__ int    d_off[EXP];
__device__ int    d_tok[EXP * MAXN];
__device__ float  d_wgt[EXP * MAXN];
__device__ int    d_slot[2 * MAXN];
__device__ int    d_tl[EXP * (MAXN / 128)];   // tile list: (e<<16)|mblock
__device__ int    d_ntl;
__device__ int    d_wq[2];                    // work counters (per GEMM)
__device__ int    d_obctr;                    // router completion counter (self-reset)
__device__ __half d_xh[(size_t)MAXN * CDIM];
__device__ __half d_w1h[(size_t)EXP * CDIM * HDIM];
__device__ __half d_w2h[(size_t)EXP * HDIM * CDIM];
__device__ __half d_hbufh[(size_t)2 * MAXN * HDIM];
__device__ __half d_ybuf[(size_t)2 * MAXN * CDIM];

__device__ __forceinline__ unsigned smem_u32(const void* p) {
    unsigned a;
    asm("{ .reg .u64 t; cvta.to.shared.u64 t, %1; cvt.u32.u64 %0, t; }"
        : "=r"(a) : "l"(p));
    return a;
}

__device__ __forceinline__ void mma_f16(float* c, const unsigned* a, const unsigned* b) {
    asm volatile(
        "mma.sync.aligned.m16n8k16.row.col.f32.f16.f16.f32 "
        "{%0,%1,%2,%3}, {%4,%5,%6,%7}, {%8,%9}, {%0,%1,%2,%3};"
        : "+f"(c[0]), "+f"(c[1]), "+f"(c[2]), "+f"(c[3])
        : "r"(a[0]), "r"(a[1]), "r"(a[2]), "r"(a[3]), "r"(b[0]), "r"(b[1]));
}

__device__ __forceinline__ void ldsm4(unsigned* r, unsigned addr) {
    asm volatile("ldmatrix.sync.aligned.m8n8.x4.shared.b16 {%0,%1,%2,%3}, [%4];"
                 : "=r"(r[0]), "=r"(r[1]), "=r"(r[2]), "=r"(r[3]) : "r"(addr));
}
__device__ __forceinline__ void ldsm4t(unsigned* r, unsigned addr) {
    asm volatile("ldmatrix.sync.aligned.m8n8.x4.trans.shared.b16 {%0,%1,%2,%3}, [%4];"
                 : "=r"(r[0]), "=r"(r[1]), "=r"(r[2]), "=r"(r[3]) : "r"(addr));
}

// ---------------------------------------------------------------------------
// fp32 -> fp16, 8 elems/thread
// ---------------------------------------------------------------------------
__global__ void cvt_half_kernel(const float* __restrict__ in, __half* __restrict__ outp,
                                long n8) {
    long i = (long)blockIdx.x * blockDim.x + threadIdx.x;
    if (i < n8) {
        const float4* s = reinterpret_cast<const float4*>(in) + i * 2;
        float4 v0 = s[0], v1 = s[1];
        __half2 h0 = __floats2half2_rn(v0.x, v0.y);
        __half2 h1 = __floats2half2_rn(v0.z, v0.w);
        __half2 h2 = __floats2half2_rn(v1.x, v1.y);
        __half2 h3 = __floats2half2_rn(v1.z, v1.w);
        uint4 o;
        o.x = *reinterpret_cast<unsigned*>(&h0);
        o.y = *reinterpret_cast<unsigned*>(&h1);
        o.z = *reinterpret_cast<unsigned*>(&h2);
        o.w = *reinterpret_cast<unsigned*>(&h3);
        reinterpret_cast<uint4*>(outp)[i] = o;
    }
}

// ---------------------------------------------------------------------------
// router: 1 warp per token. Last block builds offsets + tile list (fused).
// d_fill starts 0 (zero-init / reset by previous combine).
// ---------------------------------------------------------------------------
__global__ void router_kernel(const float* __restrict__ x,
                              const float* __restrict__ Wr, int N) {
    int gw   = (blockIdx.x * blockDim.x + threadIdx.x) >> 5;
    int lane = threadIdx.x & 31;

    if (gw < N) {
        const float* xr = x + (size_t)gw * CDIM;
        float acc[EXP];
#pragma unroll
        for (int e = 0; e < EXP; e++) acc[e] = 0.0f;
        for (int k = lane; k < CDIM; k += 32) {
            float xv = xr[k];
            const float4* w4 = reinterpret_cast<const float4*>(Wr + (size_t)k * EXP);
            float4 w0 = w4[0], w1 = w4[1];
            acc[0] += xv * w0.x; acc[1] += xv * w0.y;
            acc[2] += xv * w0.z; acc[3] += xv * w0.w;
            acc[4] += xv * w1.x; acc[5] += xv * w1.y;
            acc[6] += xv * w1.z; acc[7] += xv * w1.w;
        }
#pragma unroll
        for (int e = 0; e < EXP; e++)
#pragma unroll
            for (int off = 16; off > 0; off >>= 1)
                acc[e] += __shfl_xor_sync(0xFFFFFFFFu, acc[e], off);

        if (lane == 0) {
            float m = acc[0];
#pragma unroll
            for (int e = 1; e < EXP; e++) m = fmaxf(m, acc[e]);
            float p[EXP], s = 0.0f;
#pragma unroll
            for (int e = 0; e < EXP; e++) { p[e] = expf(acc[e] - m); s += p[e]; }
            float inv = 1.0f / s;
#pragma unroll
            for (int e = 0; e < EXP; e++) p[e] *= inv;
            int i1 = 0;
#pragma unroll
            for (int e = 1; e < EXP; e++) if (p[e] > p[i1]) i1 = e;
            int i2 = (i1 == 0) ? 1 : 0;
#pragma unroll
            for (int e = 0; e < EXP; e++)
                if (e != i1 && p[e] > p[i2]) i2 = e;
            float denom = p[i1] + p[i2] + 1e-9f;
            float w1 = p[i1] / denom, w2 = p[i2] / denom;
            int s1 = atomicAdd(&d_fill[i1], 1);
            int p1 = (i1 << 13) | s1;
            d_tok[p1] = gw; d_wgt[p1] = w1; d_slot[gw] = p1;
            int s2 = atomicAdd(&d_fill[i2], 1);
            int p2 = (i2 << 13) | s2;
            d_tok[p2] = gw; d_wgt[p2] = w2; d_slot[MAXN + gw] = p2;
        }
    }

    // ---- fused offsets: last block to finish builds tile list ----
    __syncthreads();
    if (threadIdx.x == 0) {
        __threadfence();
        int prev = atomicAdd(&d_obctr, 1);
        if (prev == (int)gridDim.x - 1) {
            d_obctr = 0;                       // self-reset for next replay
            int o = 0, m = 0;
            for (int e = 0; e < EXP; e++) {
                d_off[e] = o;
                int c = atomicAdd(&d_fill[e], 0);   // coherent read
                o += c;
                int nb = (c + 127) / 128;
                for (int mb = 0; mb < nb; mb++) d_tl[m++] = (e << 16) | mb;
            }
            d_ntl = m;
            d_wq[0] = 0;
            d_wq[1] = 0;
        }
    }
}

// ---------------------------------------------------------------------------
// Persistent fp16 mma.sync GEMM (f32 accumulate). CTA 128x256, BK=64,
// 512 thr, 16 warps (2m x 8n, warp 64x32), ldmatrix, 3-stage cp.async,
// 1 sync/iter. Tiles pulled from d_wq[MODE] (work stealing).
// MODE 0: A = gathered x rows -> gelu -> hbuf
// MODE 1: A = hbuf rows -> (y + b2) fp16 -> ybuf
// ---------------------------------------------------------------------------
#define GSMEM 148480
#define NSM 152

template<int KD, int ND, int MODE>
__global__ void __launch_bounds__(512, 1)
moe_gemm(const __half* __restrict__ Amat, const __half* __restrict__ Bmat,
         const float* __restrict__ bias) {
    constexpr int ITERS = KD / 64;
    constexpr int NJ    = ND / 256;

    extern __shared__ char smem[];
    int* stok = reinterpret_cast<int*>(smem);
    int* s_t  = reinterpret_cast<int*>(smem + 768);
    const unsigned sA = smem_u32(smem + 1024);          // 3 x 16384
    const unsigned sB = sA + 49152;                     // 3 x 32768

    const int tid = threadIdx.x;
    const int lane = tid & 31, w = tid >> 5;
    const int wm = (w & 1) * 64, wn = (w >> 1) * 32;
    const int rsel = (lane & 7) | (lane & 8);
    const int kh   = (lane >> 4) & 1;
    const int l7   = lane & 7;

    const int NT = d_ntl * NJ;

    for (;;) {
        __syncthreads();   // prior tile's smem reads complete before reuse
        if (tid == 0) *s_t = atomicAdd(&d_wq[MODE], 1);
        __syncthreads();
        const int t = *s_t;
        if (t >= NT) break;

        const int pair = d_tl[t / NJ];
        const int e    = pair >> 16;
        const int m0   = (pair & 0xFFFF) * 128;
        const int j0   = (t % NJ) * 256;
        const int cnt  = d_fill[e];
        const int off  = d_off[e];

        if (MODE == 0 && tid < 128) {
            int gm = m0 + tid;
            stok[tid] = (gm < cnt) ? d_tok[(e << 13) | gm] : -1;
        }
        __syncthreads();

        // ---- cp.async slots: A 2 chunks, B 4 chunks per thread (16B) ----
        const __half* agp[2]; unsigned aso[2], asz[2];
#pragma unroll
        for (int tt = 0; tt < 2; tt++) {
            int idx = tid + tt * 512, row = idx >> 3, c = idx & 7;
            bool ok; size_t base;
            if (MODE == 0) { int tk = stok[row]; ok = (tk >= 0); base = ok ? (size_t)tk * KD : 0; }
            else           { int gm = m0 + row;  ok = (gm < cnt); base = ok ? (size_t)(off + gm) * KD : 0; }
            agp[tt] = Amat + base + c * 8;
            asz[tt] = ok ? 16u : 0u;
            aso[tt] = row * 128 + ((c ^ (row & 7)) * 16);
        }
        const __half* bbase = Bmat + (size_t)e * CDIM * HDIM + j0;
        int bgo[4]; unsigned bso[4];
#pragma unroll
        for (int tt = 0; tt < 4; tt++) {
            int idx = tid + tt * 512, row = idx >> 5, c = idx & 31;
            bgo[tt] = row * ND + c * 8;
            bso[tt] = row * 512 + ((c ^ (row & 7)) * 16);
        }

        auto load_tile = [&](int p, int k0) {
            unsigned Ab = sA + p * 16384, Bb = sB + p * 32768;
#pragma unroll
            for (int tt = 0; tt < 2; tt++)
                asm volatile("cp.async.cg.shared.global [%0], [%1], 16, %2;"
                             :: "r"(Ab + aso[tt]), "l"(agp[tt] + k0), "r"(asz[tt]) : "memory");
            const __half* bsrc = bbase + (size_t)k0 * ND;
#pragma unroll
            for (int tt = 0; tt < 4; tt++)
                asm volatile("cp.async.cg.shared.global [%0], [%1], 16;"
                             :: "r"(Bb + bso[tt]), "l"(bsrc + bgo[tt]) : "memory");
        };

        float acc[4][4][4];
#pragma unroll
        for (int mt = 0; mt < 4; mt++)
#pragma unroll
            for (int nt = 0; nt < 4; nt++)
#pragma unroll
                for (int i = 0; i < 4; i++) acc[mt][nt][i] = 0.0f;

        load_tile(0, 0);
        asm volatile("cp.async.commit_group;" ::: "memory");
        load_tile(1, 64);
        asm volatile("cp.async.commit_group;" ::: "memory");

        for (int i = 0; i < ITERS; i++) {
            const int p = i % 3;
            asm volatile("cp.async.wait_group 1;" ::: "memory");
            __syncthreads();
            if (i + 2 < ITERS) load_tile((i + 2) % 3, (i + 2) * 64);
            asm volatile("cp.async.commit_group;" ::: "memory");

            const unsigned Ab = sA + p * 16384, Bb = sB + p * 32768;
#pragma unroll
            for (int ks = 0; ks < 4; ks++) {
                unsigned afr[4][4];
#pragma unroll
                for (int mt = 0; mt < 4; mt++) {
                    unsigned ad = Ab + (wm + mt * 16 + rsel) * 128
                                + (((ks * 2 + kh) ^ l7) * 16);
                    ldsm4(afr[mt], ad);
                }
                unsigned bfr[4][2];
#pragma unroll
                for (int bt = 0; bt < 2; bt++) {
                    int krow = ks * 16 + rsel;
                    unsigned bd = Bb + krow * 512
                                + ((((wn >> 3) + bt * 2 + kh) ^ l7) * 16);
                    unsigned r[4];
                    ldsm4t(r, bd);
                    bfr[bt * 2][0] = r[0];     bfr[bt * 2][1] = r[1];
                    bfr[bt * 2 + 1][0] = r[2]; bfr[bt * 2 + 1][1] = r[3];
                }
#pragma unroll
                for (int mt = 0; mt < 4; mt++)
#pragma unroll
                    for (int nt = 0; nt < 4; nt++)
                        mma_f16(acc[mt][nt], afr[mt], bfr[nt]);
            }
        }

        // ---- epilogue ----
#pragma unroll
        for (int mt = 0; mt < 4; mt++) {
#pragma unroll
            for (int half = 0; half < 2; half++) {
                int lrow = wm + mt * 16 + (lane >> 2) + half * 8;
                int gm   = m0 + lrow;
                if (gm >= cnt) continue;
                __half* hrow = (MODE == 0)
                    ? (d_hbufh + (size_t)(off + gm) * HDIM)
                    : (d_ybuf  + (size_t)(off + gm) * CDIM);
#pragma unroll
                for (int nt = 0; nt < 4; nt++) {
                    int col = j0 + wn + nt * 8 + (lane & 3) * 2;
                    float v0 = acc[mt][nt][half * 2 + 0] + bias[(size_t)e * ND + col];
                    float v1 = acc[mt][nt][half * 2 + 1] + bias[(size_t)e * ND + col + 1];
                    if (MODE == 0) {
                        v0 = 0.5f * v0 * (1.0f + erff(v0 * 0.70710678118654752f));
                        v1 = 0.5f * v1 * (1.0f + erff(v1 * 0.70710678118654752f));
                    }
                    *reinterpret_cast<__half2*>(hrow + col) = __floats2half2_rn(v0, v1);
                }
            }
        }
    }
}

// ---------------------------------------------------------------------------
// combine: out[tok] = w1*ybuf[row1] + w2*ybuf[row2]
// block 0 threads 0-7 additionally write utilization then reset d_fill
// ---------------------------------------------------------------------------
__global__ void combine_kernel(float* __restrict__ out, int N, int NC) {
    if (blockIdx.x == 0 && threadIdx.x < EXP) {
        int e = threadIdx.x;
        float tot = 0.0f;
        for (int j = 0; j < EXP; j++) tot += (float)d_fill[j];
        out[NC + e] = (float)d_fill[e] / (tot + 1e-9f);
        __syncwarp(0xFFu);
        d_fill[e] = 0;                 // reset for next replay
    }

    int gid  = blockIdx.x * blockDim.x + threadIdx.x;
    int col4 = gid * 4;
    int tok  = col4 / CDIM;
    int c    = col4 % CDIM;
    if (tok >= N) return;

    int p1 = d_slot[tok], p2 = d_slot[MAXN + tok];
    int r1 = d_off[p1 >> 13] + (p1 & (MAXN - 1));
    int r2 = d_off[p2 >> 13] + (p2 & (MAXN - 1));
    float w1 = d_wgt[p1], w2 = d_wgt[p2];

    const __half2* a = reinterpret_cast<const __half2*>(d_ybuf + (size_t)r1 * CDIM + c);
    const __half2* b = reinterpret_cast<const __half2*>(d_ybuf + (size_t)r2 * CDIM + c);
    float2 a0 = __half22float2(a[0]), a1 = __half22float2(a[1]);
    float2 b0 = __half22float2(b[0]), b1 = __half22float2(b[1]);
    float4 o;
    o.x = w1 * a0.x + w2 * b0.x;
    o.y = w1 * a0.y + w2 * b0.y;
    o.z = w1 * a1.x + w2 * b1.x;
    o.w = w1 * a1.y + w2 * b1.y;
    *reinterpret_cast<float4*>(out + (size_t)tok * CDIM + c) = o;
}

// ---------------------------------------------------------------------------
extern "C" void kernel_launch(void* const* d_in, const int* in_sizes, int n_in,
                              void* d_out, int out_size) {
    const float* x  = (const float*)d_in[0];
    const float* Wr = (const float*)d_in[1];
    const float* W1 = (const float*)d_in[2];
    const float* b1 = (const float*)d_in[3];
    const float* W2 = (const float*)d_in[4];
    const float* b2 = (const float*)d_in[5];
    float* out = (float*)d_out;

    int N  = in_sizes[0] / CDIM;   // 8192
    int NC = N * CDIM;

    static cudaStream_t s1 = nullptr, s2 = nullptr;
    static cudaEvent_t evRoot, evA, evW1b, evW2;
    static int init_done = 0;
    if (!init_done) {
        cudaFuncSetAttribute(moe_gemm<CDIM, HDIM, 0>,
                             cudaFuncAttributeMaxDynamicSharedMemorySize, GSMEM);
        cudaFuncSetAttribute(moe_gemm<HDIM, CDIM, 1>,
                             cudaFuncAttributeMaxDynamicSharedMemorySize, GSMEM);
        cudaStreamCreateWithFlags(&s1, cudaStreamNonBlocking);
        cudaStreamCreateWithFlags(&s2, cudaStreamNonBlocking);
        cudaEventCreateWithFlags(&evRoot, cudaEventDisableTiming);
        cudaEventCreateWithFlags(&evA, cudaEventDisableTiming);
        cudaEventCreateWithFlags(&evW1b, cudaEventDisableTiming);
        cudaEventCreateWithFlags(&evW2, cudaEventDisableTiming);
        init_done = 1;
    }

    __half *xh, *w1h, *w2h;
    cudaGetSymbolAddress((void**)&xh,  d_xh);
    cudaGetSymbolAddress((void**)&w1h, d_w1h);
    cudaGetSymbolAddress((void**)&w2h, d_w2h);

    // ---- fork: converts on s1/s2, routing (with fused offsets) on main ----
    cudaEventRecord(evRoot, 0);
    cudaStreamWaitEvent(s1, evRoot, 0);
    cudaStreamWaitEvent(s2, evRoot, 0);

    router_kernel<<<(N + 7) / 8, 256>>>(x, Wr, N);

    {
        long nw  = (long)EXP * CDIM * HDIM;      // elements per weight tensor
        long h8  = nw / 2 / 8;                   // 8-elem chunks per half
        // s1: x cvt then W1 first half ; s2: W1 second half then W2
        cvt_half_kernel<<<(NC / 8 + 255) / 256, 256, 0, s1>>>(x, xh, NC / 8);
        cvt_half_kernel<<<(int)((h8 + 255) / 256), 256, 0, s1>>>(W1, w1h, h8);
        cudaEventRecord(evA, s1);
        cvt_half_kernel<<<(int)((h8 + 255) / 256), 256, 0, s2>>>(W1 + nw / 2, w1h + nw / 2, h8);
        cudaEventRecord(evW1b, s2);
        cvt_half_kernel<<<(int)((nw / 8 + 255) / 256), 256, 0, s2>>>(W2, w2h, nw / 8);
        cudaEventRecord(evW2, s2);
    }

    // ---- gemm1: needs routing (main order), xh + W1a (evA), W1b (evW1b) ----
    cudaStreamWaitEvent(0, evA, 0);
    cudaStreamWaitEvent(0, evW1b, 0);
    moe_gemm<CDIM, HDIM, 0><<<NSM, 512, GSMEM>>>(xh, w1h, b1);

    // ---- gemm2: needs w2h ----
    cudaStreamWaitEvent(0, evW2, 0);
    __half* hb; cudaGetSymbolAddress((void**)&hb, d_hbufh);
    moe_gemm<HDIM, CDIM, 1><<<NSM, 512, GSMEM>>>(hb, w2h, b2);

    // ---- combine (+ fused util + d_fill reset) ----
    combine_kernel<<<(NC / 4 + 255) / 256, 256>>>(out, N, NC);
}